// round 2
// baseline (speedup 1.0000x reference)
#include <cuda_runtime.h>
#include <cstdint>

// ---------------------------------------------------------------------------
// RuleModel: differentiable logic gate network forward pass.
// Collapses to column-gather gates:
//   gate col j selects input col argmax_i(w[i,j]+g[i,j])
//   AND: c = a*b ; OR: d = 1-(1-a)(1-b)
// h widths: h0=1026, h1=3074 (=h0|c|d), h2=5122 (=h1|c|d), h3=1024 (=c|d)
// out[r] = sum_j lin_w[j]*h3[r,j]
// ---------------------------------------------------------------------------

#define NIDX 10240            // 4*1024 + 4*1024 + 4*512
__device__ int g_idx[NIDX];

struct AmArgs {
    const float* w[12];
    const float* gp[12];
    int din[12], dout[12], off[12];
};

// Column-wise argmax of w+g. Block = 32 cols x 8 row-groups.
__global__ void __launch_bounds__(256) argmax_kernel(AmArgs a) {
    __shared__ float sb[256];
    __shared__ int   si[256];
    int p    = blockIdx.y;
    int dout = a.dout[p];
    int lane = threadIdx.x & 31;
    int rg   = threadIdx.x >> 5;
    int col  = blockIdx.x * 32 + lane;

    float best = -3.4e38f;
    int bi = 0;
    if (col < dout) {
        const float* __restrict__ w = a.w[p];
        const float* __restrict__ g = a.gp[p];
        int din = a.din[p];
        size_t base = (size_t)rg * dout + col;
        size_t step = (size_t)dout * 8;
        int i = rg;
        for (; i + 32 <= din; i += 32) {
            #pragma unroll
            for (int u = 0; u < 4; u++) {
                float v = __ldg(w + base) + __ldg(g + base);
                if (v > best) { best = v; bi = i + u * 8; }
                base += step;
            }
        }
        for (; i < din; i += 8) {
            float v = __ldg(w + base) + __ldg(g + base);
            if (v > best) { best = v; bi = i; }
            base += step;
        }
    }
    sb[threadIdx.x] = best;
    si[threadIdx.x] = bi;
    __syncthreads();
    if (rg == 0 && col < dout) {
        #pragma unroll
        for (int k = 1; k < 8; k++) {
            float v  = sb[k * 32 + lane];
            int   vi = si[k * 32 + lane];
            // max; tie -> smallest row index (matches jnp.argmax first-occurrence)
            if (v > best || (v == best && vi < bi)) { best = v; bi = vi; }
        }
        g_idx[a.off[p] + col] = bi;
    }
}

// ---------------------------------------------------------------------------

__device__ __forceinline__ float4 f4and(float4 a, float4 b) {
    return make_float4(a.x * b.x, a.y * b.y, a.z * b.z, a.w * b.w);
}
__device__ __forceinline__ float4 f4or(float4 a, float4 b) {
    return make_float4(1.0f - (1.0f - a.x) * (1.0f - b.x),
                       1.0f - (1.0f - a.y) * (1.0f - b.y),
                       1.0f - (1.0f - a.z) * (1.0f - b.z),
                       1.0f - (1.0f - a.w) * (1.0f - b.w));
}

#define HW 5122
#define SMEM_BYTES (2 * HW * 16 + 8 * 512 * 4)   // h4 + xs = 180288

// 8 rows per CTA. h stored [col][row8] as 2x float4 per column.
__global__ void __launch_bounds__(256) logic_kernel(
        const float* __restrict__ x, const float* __restrict__ lw,
        float* __restrict__ out) {
    extern __shared__ float4 h4[];
    float* xs = (float*)(h4 + 2 * HW);       // 8 x 512 staging / reduce scratch
    int tid = threadIdx.x;
    long row0 = (long)blockIdx.x * 8;

    // --- stage x tile (8 rows x 512 cols), coalesced ---
    const float4* x4 = (const float4*)x + row0 * 128;
    float4* xs4 = (float4*)xs;
    #pragma unroll
    for (int i = 0; i < 4; i++) xs4[tid + i * 256] = x4[tid + i * 256];
    __syncthreads();

    // --- transpose into h0: cols 0..511 = x, 512..1023 = 1-x, 1024=1, 1025=0 ---
    #pragma unroll
    for (int cc = 0; cc < 2; cc++) {
        int c = tid + cc * 256;
        float4 lo, hi;
        lo.x = xs[c];        lo.y = xs[c + 512];  lo.z = xs[c + 1024]; lo.w = xs[c + 1536];
        hi.x = xs[c + 2048]; hi.y = xs[c + 2560]; hi.z = xs[c + 3072]; hi.w = xs[c + 3584];
        h4[2 * c]     = lo;
        h4[2 * c + 1] = hi;
        h4[2 * (c + 512)]     = make_float4(1.f - lo.x, 1.f - lo.y, 1.f - lo.z, 1.f - lo.w);
        h4[2 * (c + 512) + 1] = make_float4(1.f - hi.x, 1.f - hi.y, 1.f - hi.z, 1.f - hi.w);
    }
    if (tid < 2) {
        float v = tid ? 0.f : 1.f;
        float4 f = make_float4(v, v, v, v);
        h4[2 * (1024 + tid)]     = f;
        h4[2 * (1024 + tid) + 1] = f;
    }
    __syncthreads();

    // --- layers 1 & 2: 1024 AND + 1024 OR gates each ---
    #pragma unroll 1
    for (int L = 0; L < 2; L++) {
        int iof   = L * 4096;
        int cbase = L ? 3074 : 1026;
        int dbase = L ? 4098 : 2050;
        #pragma unroll 2
        for (int j = tid; j < 1024; j += 256) {
            int i1 = g_idx[iof + j];
            int i2 = g_idx[iof + 1024 + j];
            int i3 = g_idx[iof + 2048 + j];
            int i4 = g_idx[iof + 3072 + j];
            float4 a0 = h4[2 * i1], a1 = h4[2 * i1 + 1];
            float4 b0 = h4[2 * i2], b1 = h4[2 * i2 + 1];
            float4 p0 = h4[2 * i3], p1 = h4[2 * i3 + 1];
            float4 q0 = h4[2 * i4], q1 = h4[2 * i4 + 1];
            h4[2 * (cbase + j)]     = f4and(a0, b0);
            h4[2 * (cbase + j) + 1] = f4and(a1, b1);
            h4[2 * (dbase + j)]     = f4or(p0, q0);
            h4[2 * (dbase + j) + 1] = f4or(p1, q1);
        }
        __syncthreads();
    }

    // --- layer 3 (512 AND + 512 OR) fused with lin_w dot ---
    float4 aL = make_float4(0, 0, 0, 0), aH = make_float4(0, 0, 0, 0);
    #pragma unroll
    for (int jj = 0; jj < 2; jj++) {
        int j = tid + jj * 256;
        int i1 = g_idx[8192 + j], i2 = g_idx[8704 + j];
        int i3 = g_idx[9216 + j], i4 = g_idx[9728 + j];
        float wA = __ldg(lw + j), wD = __ldg(lw + 512 + j);
        float4 a0 = h4[2 * i1], a1 = h4[2 * i1 + 1];
        float4 b0 = h4[2 * i2], b1 = h4[2 * i2 + 1];
        float4 p0 = h4[2 * i3], p1 = h4[2 * i3 + 1];
        float4 q0 = h4[2 * i4], q1 = h4[2 * i4 + 1];
        float4 c0 = f4and(a0, b0), c1 = f4and(a1, b1);
        float4 d0 = f4or(p0, q0),  d1 = f4or(p1, q1);
        aL.x += wA * c0.x + wD * d0.x;  aL.y += wA * c0.y + wD * d0.y;
        aL.z += wA * c0.z + wD * d0.z;  aL.w += wA * c0.w + wD * d0.w;
        aH.x += wA * c1.x + wD * d1.x;  aH.y += wA * c1.y + wD * d1.y;
        aH.z += wA * c1.z + wD * d1.z;  aH.w += wA * c1.w + wD * d1.w;
    }

    // --- reduce 256 threads -> 8 row sums ---
    #pragma unroll
    for (int o = 16; o; o >>= 1) {
        aL.x += __shfl_xor_sync(0xffffffffu, aL.x, o);
        aL.y += __shfl_xor_sync(0xffffffffu, aL.y, o);
        aL.z += __shfl_xor_sync(0xffffffffu, aL.z, o);
        aL.w += __shfl_xor_sync(0xffffffffu, aL.w, o);
        aH.x += __shfl_xor_sync(0xffffffffu, aH.x, o);
        aH.y += __shfl_xor_sync(0xffffffffu, aH.y, o);
        aH.z += __shfl_xor_sync(0xffffffffu, aH.z, o);
        aH.w += __shfl_xor_sync(0xffffffffu, aH.w, o);
    }
    float* red = xs;   // xs no longer needed
    if ((tid & 31) == 0) {
        int w = tid >> 5;
        red[w * 8 + 0] = aL.x; red[w * 8 + 1] = aL.y;
        red[w * 8 + 2] = aL.z; red[w * 8 + 3] = aL.w;
        red[w * 8 + 4] = aH.x; red[w * 8 + 5] = aH.y;
        red[w * 8 + 6] = aH.z; red[w * 8 + 7] = aH.w;
    }
    __syncthreads();
    if (tid < 8) {
        float s = 0.f;
        #pragma unroll
        for (int k = 0; k < 8; k++) s += red[k * 8 + tid];
        out[row0 + tid] = s;
    }
}

// ---------------------------------------------------------------------------

extern "C" void kernel_launch(void* const* d_in, const int* in_sizes, int n_in,
                              void* d_out, int out_size) {
    (void)out_size;
    const float* x  = nullptr;
    const float* lw = nullptr;
    const float* L1[8] = {0}; const float* L2[8] = {0}; const float* L3[8] = {0};
    int n1 = 0, n2 = 0, n3 = 0;
    for (int i = 0; i < n_in; i++) {
        switch (in_sizes[i]) {
            case 16777216: x = (const float*)d_in[i]; break;                 // x (32768,512)
            case 1050624:  if (n1 < 8) L1[n1++] = (const float*)d_in[i]; break;  // (1026,1024)
            case 3147776:  if (n2 < 8) L2[n2++] = (const float*)d_in[i]; break;  // (3074,1024)
            case 2622464:  if (n3 < 8) L3[n3++] = (const float*)d_in[i]; break;  // (5122,512)
            case 1024:     lw = (const float*)d_in[i]; break;                // lin_w
            default: break;                                                  // tau (ignored)
        }
    }

    AmArgs a;
    for (int k = 0; k < 4; k++) {
        a.w[k]      = L1[k]; a.gp[k]     = L1[4 + k];
        a.din[k]    = 1026;  a.dout[k]   = 1024;  a.off[k]   = k * 1024;
        a.w[4 + k]  = L2[k]; a.gp[4 + k] = L2[4 + k];
        a.din[4+k]  = 3074;  a.dout[4+k] = 1024;  a.off[4+k] = 4096 + k * 1024;
        a.w[8 + k]  = L3[k]; a.gp[8 + k] = L3[4 + k];
        a.din[8+k]  = 5122;  a.dout[8+k] = 512;   a.off[8+k] = 8192 + k * 512;
    }

    argmax_kernel<<<dim3(32, 12), 256>>>(a);

    cudaFuncSetAttribute(logic_kernel,
                         cudaFuncAttributeMaxDynamicSharedMemorySize, SMEM_BYTES);
    logic_kernel<<<4096, 256, SMEM_BYTES>>>(x, lw, (float*)d_out);
}

// round 4
// speedup vs baseline: 1.4121x; 1.4121x over previous
#include <cuda_runtime.h>
#include <cstdint>

// ---------------------------------------------------------------------------
// RuleModel: logic-gate network. Gates are column gathers chosen by
// argmax_i(w[i,j]+g[i,j]). AND: a*b ; OR: 1-(1-a)(1-b).
// h widths: h0=1026, h1=3074, h2=5122, h3=1024; out = h3 @ lin_w.
//
// Pipeline: argmax_part (balanced partial argmax) -> argmax_reduce ->
// plan (backward reachability: only gates whose outputs are ever read get
// computed) -> logic (8 rows/CTA, h[col][row8] in SMEM, gathers).
// ---------------------------------------------------------------------------

#define NIDX 10240
__device__ int g_idx[NIDX];
// g_idx layout: L1 c1,c2,d1,d2 @ 0,1024,2048,3072
//               L2 c1,c2,d1,d2 @ 4096,5120,6144,7168
//               L3 c1,c2,d1,d2 @ 8192,8704,9216,9728 (512 each)

__device__ unsigned long long g_part[12 * 11 * 1024];

__device__ unsigned char g_act1[2048];   // [c1 0..1023 | d1 0..1023]
__device__ unsigned char g_act2[2048];
__device__ int4 g_l1a[1024], g_l1o[1024], g_l2a[1024], g_l2o[1024];
__device__ int  g_n[4];

struct AmArgs {
    const float* w[12];
    const float* gp[12];
    int din[12], dout[12];
};

// ---- stage 1: partial argmax over 512-row segments (balanced) --------------
__global__ void __launch_bounds__(256) argmax_part(AmArgs a) {
    int p    = blockIdx.z;
    int dout = a.dout[p];
    int din  = a.din[p];
    if ((int)blockIdx.x * 32 >= dout) return;
    int r0 = blockIdx.y * 512;
    if (r0 >= din) return;
    int rend = min(r0 + 512, din);

    int lane = threadIdx.x & 31;
    int rg   = threadIdx.x >> 5;
    int col  = blockIdx.x * 32 + lane;

    const float* __restrict__ w = a.w[p];
    const float* __restrict__ g = a.gp[p];

    unsigned long long best = 0ull;
    size_t base = (size_t)(r0 + rg) * dout + col;
    size_t step = (size_t)dout * 8;
    for (int r = r0 + rg; r < rend; r += 8, base += step) {
        float v = __ldg(w + base) + __ldg(g + base);
        unsigned u = __float_as_uint(v);
        u = (u & 0x80000000u) ? ~u : (u | 0x80000000u);
        unsigned long long key =
            ((unsigned long long)u << 32) | (unsigned)(~(unsigned)r);
        best = max(best, key);
    }

    __shared__ unsigned long long sb[256];
    sb[threadIdx.x] = best;
    __syncthreads();
    if (rg == 0) {
        #pragma unroll
        for (int k = 1; k < 8; k++) best = max(best, sb[k * 32 + lane]);
        g_part[(p * 11 + blockIdx.y) * 1024 + col] = best;
    }
}

// ---- stage 2: reduce segments -> g_idx -------------------------------------
__global__ void __launch_bounds__(256) argmax_reduce() {
    int t = blockIdx.x * 256 + threadIdx.x;
    if (t >= NIDX) return;
    int p, col;
    if (t < 4096)      { p = t >> 10;                col = t & 1023; }
    else if (t < 8192) { p = 4 + ((t - 4096) >> 10); col = t & 1023; }
    else               { p = 8 + ((t - 8192) >> 9);  col = (t - 8192) & 511; }
    int nseg = (p < 4) ? 3 : (p < 8) ? 7 : 11;
    unsigned long long best = 0ull;
    for (int s = 0; s < nseg; s++)
        best = max(best, g_part[(p * 11 + s) * 1024 + col]);
    g_idx[t] = (int)(~(unsigned)(best & 0xFFFFFFFFull));
}

// ---- plan: backward reachability + compacted gate lists --------------------
__global__ void __launch_bounds__(1024) plan_kernel() {
    int t = threadIdx.x;
    if (t < 4) g_n[t] = 0;
    g_act1[t] = 0; g_act1[t + 1024] = 0;
    g_act2[t] = 0; g_act2[t + 1024] = 0;
    __syncthreads();

    // mark from L3 refs: c2/d2 cols (>=3074) and direct h1 c1/d1 cols
    #pragma unroll
    for (int k = 0; k < 2; k++) {
        int v = g_idx[8192 + k * 1024 + t];
        if (v >= 3074)      g_act2[v - 3074] = 1;
        else if (v >= 1026) g_act1[v - 1026] = 1;
    }
    __syncthreads();

    // active L2 gates mark their h1 operands
    if (g_act2[t]) {
        int v = g_idx[4096 + t]; if (v >= 1026) g_act1[v - 1026] = 1;
        v     = g_idx[5120 + t]; if (v >= 1026) g_act1[v - 1026] = 1;
    }
    if (g_act2[1024 + t]) {
        int v = g_idx[6144 + t]; if (v >= 1026) g_act1[v - 1026] = 1;
        v     = g_idx[7168 + t]; if (v >= 1026) g_act1[v - 1026] = 1;
    }
    __syncthreads();

    // compact (order nondeterministic; outputs are a pure scatter -> ok)
    if (g_act1[t]) {
        int p = atomicAdd(&g_n[0], 1);
        g_l1a[p] = make_int4(1026 + t, g_idx[t], g_idx[1024 + t], 0);
    }
    if (g_act1[1024 + t]) {
        int p = atomicAdd(&g_n[1], 1);
        g_l1o[p] = make_int4(2050 + t, g_idx[2048 + t], g_idx[3072 + t], 0);
    }
    if (g_act2[t]) {
        int p = atomicAdd(&g_n[2], 1);
        g_l2a[p] = make_int4(3074 + t, g_idx[4096 + t], g_idx[5120 + t], 0);
    }
    if (g_act2[1024 + t]) {
        int p = atomicAdd(&g_n[3], 1);
        g_l2o[p] = make_int4(4098 + t, g_idx[6144 + t], g_idx[7168 + t], 0);
    }
}

// ---------------------------------------------------------------------------

__device__ __forceinline__ float4 f4and(float4 a, float4 b) {
    return make_float4(a.x * b.x, a.y * b.y, a.z * b.z, a.w * b.w);
}
__device__ __forceinline__ float4 f4or(float4 a, float4 b) {
    return make_float4(1.0f - (1.0f - a.x) * (1.0f - b.x),
                       1.0f - (1.0f - a.y) * (1.0f - b.y),
                       1.0f - (1.0f - a.z) * (1.0f - b.z),
                       1.0f - (1.0f - a.w) * (1.0f - b.w));
}

#define HW 5122
#define SMEM_BYTES (2 * HW * 16 + 8 * 512 * 4)   // h4 + xs = 180288

// 8 rows per CTA, 512 threads (16 warps). h stored [col][row8] as 2x float4.
__global__ void __launch_bounds__(512) logic_kernel(
        const float* __restrict__ x, const float* __restrict__ lw,
        float* __restrict__ out) {
    extern __shared__ float4 h4[];
    float* xs = (float*)(h4 + 2 * HW);
    int tid = threadIdx.x;
    long row0 = (long)blockIdx.x * 8;

    // stage x tile (8 rows x 512 cols), coalesced
    const float4* x4 = (const float4*)x + row0 * 128;
    float4* xs4 = (float4*)xs;
    xs4[tid]       = x4[tid];
    xs4[tid + 512] = x4[tid + 512];
    __syncthreads();

    // transpose into h0: cols 0..511 = x, 512..1023 = 1-x, 1024=1, 1025=0
    {
        int c = tid;
        float4 lo, hi;
        lo.x = xs[c];        lo.y = xs[c + 512];  lo.z = xs[c + 1024]; lo.w = xs[c + 1536];
        hi.x = xs[c + 2048]; hi.y = xs[c + 2560]; hi.z = xs[c + 3072]; hi.w = xs[c + 3584];
        h4[2 * c]     = lo;
        h4[2 * c + 1] = hi;
        h4[2 * (c + 512)]     = make_float4(1.f - lo.x, 1.f - lo.y, 1.f - lo.z, 1.f - lo.w);
        h4[2 * (c + 512) + 1] = make_float4(1.f - hi.x, 1.f - hi.y, 1.f - hi.z, 1.f - hi.w);
    }
    if (tid < 2) {
        float v = tid ? 0.f : 1.f;
        float4 f = make_float4(v, v, v, v);
        h4[2 * (1024 + tid)]     = f;
        h4[2 * (1024 + tid) + 1] = f;
    }
    __syncthreads();

    int n1a = g_n[0], n1o = g_n[1], n2a = g_n[2], n2o = g_n[3];

    // layer 1 (active gates only)
    for (int g = tid; g < n1a; g += 512) {
        int4 r = g_l1a[g];
        float4 a0 = h4[2 * r.y], a1 = h4[2 * r.y + 1];
        float4 b0 = h4[2 * r.z], b1 = h4[2 * r.z + 1];
        h4[2 * r.x]     = f4and(a0, b0);
        h4[2 * r.x + 1] = f4and(a1, b1);
    }
    for (int g = tid; g < n1o; g += 512) {
        int4 r = g_l1o[g];
        float4 a0 = h4[2 * r.y], a1 = h4[2 * r.y + 1];
        float4 b0 = h4[2 * r.z], b1 = h4[2 * r.z + 1];
        h4[2 * r.x]     = f4or(a0, b0);
        h4[2 * r.x + 1] = f4or(a1, b1);
    }
    __syncthreads();

    // layer 2 (active gates only)
    for (int g = tid; g < n2a; g += 512) {
        int4 r = g_l2a[g];
        float4 a0 = h4[2 * r.y], a1 = h4[2 * r.y + 1];
        float4 b0 = h4[2 * r.z], b1 = h4[2 * r.z + 1];
        h4[2 * r.x]     = f4and(a0, b0);
        h4[2 * r.x + 1] = f4and(a1, b1);
    }
    for (int g = tid; g < n2o; g += 512) {
        int4 r = g_l2o[g];
        float4 a0 = h4[2 * r.y], a1 = h4[2 * r.y + 1];
        float4 b0 = h4[2 * r.z], b1 = h4[2 * r.z + 1];
        h4[2 * r.x]     = f4or(a0, b0);
        h4[2 * r.x + 1] = f4or(a1, b1);
    }
    __syncthreads();

    // layer 3 (all 1024 gates) fused with lin_w dot. 512 threads: gate j = tid.
    float4 aL = make_float4(0, 0, 0, 0), aH = make_float4(0, 0, 0, 0);
    {
        int j = tid;
        int i1 = g_idx[8192 + j], i2 = g_idx[8704 + j];
        int i3 = g_idx[9216 + j], i4 = g_idx[9728 + j];
        float wA = __ldg(lw + j), wD = __ldg(lw + 512 + j);
        float4 a0 = h4[2 * i1], a1 = h4[2 * i1 + 1];
        float4 b0 = h4[2 * i2], b1 = h4[2 * i2 + 1];
        float4 p0 = h4[2 * i3], p1 = h4[2 * i3 + 1];
        float4 q0 = h4[2 * i4], q1 = h4[2 * i4 + 1];
        float4 c0 = f4and(a0, b0), c1 = f4and(a1, b1);
        float4 d0 = f4or(p0, q0),  d1 = f4or(p1, q1);
        aL.x += wA * c0.x + wD * d0.x;  aL.y += wA * c0.y + wD * d0.y;
        aL.z += wA * c0.z + wD * d0.z;  aL.w += wA * c0.w + wD * d0.w;
        aH.x += wA * c1.x + wD * d1.x;  aH.y += wA * c1.y + wD * d1.y;
        aH.z += wA * c1.z + wD * d1.z;  aH.w += wA * c1.w + wD * d1.w;
    }

    // reduce 16 warps -> 8 row sums
    #pragma unroll
    for (int o = 16; o; o >>= 1) {
        aL.x += __shfl_xor_sync(0xffffffffu, aL.x, o);
        aL.y += __shfl_xor_sync(0xffffffffu, aL.y, o);
        aL.z += __shfl_xor_sync(0xffffffffu, aL.z, o);
        aL.w += __shfl_xor_sync(0xffffffffu, aL.w, o);
        aH.x += __shfl_xor_sync(0xffffffffu, aH.x, o);
        aH.y += __shfl_xor_sync(0xffffffffu, aH.y, o);
        aH.z += __shfl_xor_sync(0xffffffffu, aH.z, o);
        aH.w += __shfl_xor_sync(0xffffffffu, aH.w, o);
    }
    float* red = xs;
    if ((tid & 31) == 0) {
        int w = tid >> 5;
        red[w * 8 + 0] = aL.x; red[w * 8 + 1] = aL.y;
        red[w * 8 + 2] = aL.z; red[w * 8 + 3] = aL.w;
        red[w * 8 + 4] = aH.x; red[w * 8 + 5] = aH.y;
        red[w * 8 + 6] = aH.z; red[w * 8 + 7] = aH.w;
    }
    __syncthreads();
    if (tid < 8) {
        float s = 0.f;
        #pragma unroll
        for (int k = 0; k < 16; k++) s += red[k * 8 + tid];
        out[row0 + tid] = s;
    }
}

// ---------------------------------------------------------------------------

extern "C" void kernel_launch(void* const* d_in, const int* in_sizes, int n_in,
                              void* d_out, int out_size) {
    (void)out_size;
    const float* x  = nullptr;
    const float* lw = nullptr;
    const float* L1[8] = {0}; const float* L2[8] = {0}; const float* L3[8] = {0};
    int n1 = 0, n2 = 0, n3 = 0;
    for (int i = 0; i < n_in; i++) {
        switch (in_sizes[i]) {
            case 16777216: x = (const float*)d_in[i]; break;                     // x
            case 1050624:  if (n1 < 8) L1[n1++] = (const float*)d_in[i]; break;  // (1026,1024)
            case 3147776:  if (n2 < 8) L2[n2++] = (const float*)d_in[i]; break;  // (3074,1024)
            case 2622464:  if (n3 < 8) L3[n3++] = (const float*)d_in[i]; break;  // (5122,512)
            case 1024:     lw = (const float*)d_in[i]; break;                    // lin_w
            default: break;                                                      // tau
        }
    }

    AmArgs a;
    for (int k = 0; k < 4; k++) {
        a.w[k]     = L1[k]; a.gp[k]     = L1[4 + k]; a.din[k]     = 1026; a.dout[k]     = 1024;
        a.w[4 + k] = L2[k]; a.gp[4 + k] = L2[4 + k]; a.din[4 + k] = 3074; a.dout[4 + k] = 1024;
        a.w[8 + k] = L3[k]; a.gp[8 + k] = L3[4 + k]; a.din[8 + k] = 5122; a.dout[8 + k] = 512;
    }

    argmax_part<<<dim3(32, 11, 12), 256>>>(a);
    argmax_reduce<<<40, 256>>>();
    plan_kernel<<<1, 1024>>>();

    cudaFuncSetAttribute(logic_kernel,
                         cudaFuncAttributeMaxDynamicSharedMemorySize, SMEM_BYTES);
    logic_kernel<<<4096, 512, SMEM_BYTES>>>(x, lw, (float*)d_out);
}